// round 7
// baseline (speedup 1.0000x reference)
#include <cuda_runtime.h>
#include <cuda_bf16.h>
#include <cstdint>
#include <math.h>

#define B_ 2
#define N_ 2048
#define E_ 1024
#define H_ 16
#define D_ 64
#define THREE_E 3072
#define M_ROWS 4096   // B*N

// ---------------------------------------------------------------------------
// Scratch (__device__ globals; allocation-free rule)
// ---------------------------------------------------------------------------
__device__ __nv_bfloat16 g_a_hi[(size_t)M_ROWS * E_];        // x split, then attn-out split
__device__ __nv_bfloat16 g_a_lo[(size_t)M_ROWS * E_];
__device__ __nv_bfloat16 g_qkv_hi[(size_t)M_ROWS * THREE_E]; // qkv split (gemm1 out)
__device__ __nv_bfloat16 g_qkv_lo[(size_t)M_ROWS * THREE_E];
__device__ __nv_bfloat16 g_wq_hi[(size_t)THREE_E * E_];      // w_qkv^T [Nc,K]
__device__ __nv_bfloat16 g_wq_lo[(size_t)THREE_E * E_];
__device__ __nv_bfloat16 g_wp_hi[(size_t)E_ * E_];           // w_proj^T
__device__ __nv_bfloat16 g_wp_lo[(size_t)E_ * E_];

// ---------------------------------------------------------------------------
// PTX helpers (sm_80+, valid on plain compute_100)
// ---------------------------------------------------------------------------
__device__ __forceinline__ void mma16816(float* c, const uint32_t* a, const uint32_t* b) {
    asm volatile(
        "mma.sync.aligned.m16n8k16.row.col.f32.bf16.bf16.f32 "
        "{%0,%1,%2,%3}, {%4,%5,%6,%7}, {%8,%9}, {%0,%1,%2,%3};"
        : "+f"(c[0]), "+f"(c[1]), "+f"(c[2]), "+f"(c[3])
        : "r"(a[0]), "r"(a[1]), "r"(a[2]), "r"(a[3]), "r"(b[0]), "r"(b[1]));
}
__device__ __forceinline__ uint32_t lds_u32(const __nv_bfloat16* p) {
    return *reinterpret_cast<const uint32_t*>(p);
}
__device__ __forceinline__ void ldmx4_trans(uint32_t* r, uint32_t addr) {
    asm volatile("ldmatrix.sync.aligned.m8n8.x4.trans.shared.b16 {%0,%1,%2,%3}, [%4];"
                 : "=r"(r[0]), "=r"(r[1]), "=r"(r[2]), "=r"(r[3]) : "r"(addr));
}
__device__ __forceinline__ uint32_t smem_u32(const void* p) {
    uint32_t a;
    asm("{ .reg .u64 t; cvta.to.shared.u64 t, %1; cvt.u32.u64 %0, t; }"
        : "=r"(a) : "l"(p));
    return a;
}
__device__ __forceinline__ uint32_t pack_bf16(float a, float b) {
    __nv_bfloat162 v = __floats2bfloat162_rn(a, b);
    return *reinterpret_cast<uint32_t*>(&v);
}
__device__ __forceinline__ void cp_async16(void* smem_dst, const void* gsrc) {
    uint32_t d = smem_u32(smem_dst);
    asm volatile("cp.async.cg.shared.global [%0], [%1], 16;" :: "r"(d), "l"(gsrc));
}
#define CP_COMMIT() asm volatile("cp.async.commit_group;" ::: "memory")
#define CP_WAIT(n)  asm volatile("cp.async.wait_group %0;" :: "n"(n) : "memory")

// ---------------------------------------------------------------------------
// Prep kernels
// ---------------------------------------------------------------------------
__global__ void split_f32(const float* __restrict__ src,
                          __nv_bfloat16* __restrict__ hi,
                          __nv_bfloat16* __restrict__ lo, int n)
{
    int i = blockIdx.x * blockDim.x + threadIdx.x;
    if (i < n) {
        float x = src[i];
        __nv_bfloat16 h = __float2bfloat16(x);
        hi[i] = h;
        lo[i] = __float2bfloat16(x - __bfloat162float(h));
    }
}

__global__ void transpose_split(const float* __restrict__ w,
                                __nv_bfloat16* __restrict__ thi,
                                __nv_bfloat16* __restrict__ tlo,
                                int K, int Nc)
{
    __shared__ float t[32][33];
    int n0 = blockIdx.x * 32, k0 = blockIdx.y * 32;
    int tx = threadIdx.x, ty = threadIdx.y;     // 32 x 8
#pragma unroll
    for (int i = 0; i < 32; i += 8)
        t[ty + i][tx] = w[(size_t)(k0 + ty + i) * Nc + n0 + tx];
    __syncthreads();
#pragma unroll
    for (int i = 0; i < 32; i += 8) {
        float v = t[tx][ty + i];
        __nv_bfloat16 h = __float2bfloat16(v);
        size_t o = (size_t)(n0 + ty + i) * K + k0 + tx;
        thi[o] = h;
        tlo[o] = __float2bfloat16(v - __bfloat162float(h));
    }
}

// ---------------------------------------------------------------------------
// Split-bf16 GEMM with 2-stage cp.async pipeline.
// CTA: 128x128 tile, 256 thr (8 warps, 2m x 4n), K chunk 64 double-buffered.
// ---------------------------------------------------------------------------
#define AS_ 72
#define TILE_ELEMS (128 * AS_)
#define STAGE_ELEMS (4 * TILE_ELEMS)
#define GEMM_SMEM (2 * STAGE_ELEMS * 2)   // 147456 B

__device__ __forceinline__ void cp_tile_g(const __nv_bfloat16* __restrict__ src,
                                          int row0, int K, int k0,
                                          __nv_bfloat16* dst, int tid)
{
#pragma unroll
    for (int it = 0; it < 4; it++) {
        int idx = tid + it * 256;
        int r = idx >> 3, g = idx & 7;
        cp_async16(dst + r * AS_ + g * 8,
                   src + (size_t)(row0 + r) * K + k0 + g * 8);
    }
}

__global__ void __launch_bounds__(256, 1)
gemm_mma(const __nv_bfloat16* __restrict__ a_hi,
         const __nv_bfloat16* __restrict__ a_lo,
         const __nv_bfloat16* __restrict__ b_hi,
         const __nv_bfloat16* __restrict__ b_lo,
         const float* __restrict__ bias,
         float* __restrict__ C,
         __nv_bfloat16* __restrict__ Chi,
         __nv_bfloat16* __restrict__ Clo,
         int Nc, int K, int split_out)
{
    extern __shared__ __nv_bfloat16 sm[];

    const int tid  = threadIdx.x;
    const int wid  = tid >> 5;
    const int lane = tid & 31;
    const int wm   = wid >> 2;
    const int wn   = wid & 3;
    const int m0   = blockIdx.y * 128;
    const int n0   = blockIdx.x * 128;
    const int lr = lane >> 2;
    const int lc = (lane & 3) * 2;

    float acc[4][4][4];
#pragma unroll
    for (int i = 0; i < 4; i++)
#pragma unroll
        for (int j = 0; j < 4; j++)
#pragma unroll
            for (int q = 0; q < 4; q++) acc[i][j][q] = 0.f;

    const int nchunk = K >> 6;

    // Prologue: issue chunk 0 into stage 0
    {
        __nv_bfloat16* st = sm;
        cp_tile_g(a_hi, m0, K, 0, st, tid);
        cp_tile_g(a_lo, m0, K, 0, st + TILE_ELEMS, tid);
        cp_tile_g(b_hi, n0, K, 0, st + 2 * TILE_ELEMS, tid);
        cp_tile_g(b_lo, n0, K, 0, st + 3 * TILE_ELEMS, tid);
        CP_COMMIT();
    }

    for (int c = 0; c < nchunk; c++) {
        if (c + 1 < nchunk) {
            __nv_bfloat16* st = sm + ((c + 1) & 1) * STAGE_ELEMS;
            const int k1 = (c + 1) << 6;
            cp_tile_g(a_hi, m0, K, k1, st, tid);
            cp_tile_g(a_lo, m0, K, k1, st + TILE_ELEMS, tid);
            cp_tile_g(b_hi, n0, K, k1, st + 2 * TILE_ELEMS, tid);
            cp_tile_g(b_lo, n0, K, k1, st + 3 * TILE_ELEMS, tid);
            CP_COMMIT();
            CP_WAIT(1);
        } else {
            CP_WAIT(0);
        }
        __syncthreads();

        __nv_bfloat16* Ah = sm + (c & 1) * STAGE_ELEMS;
        __nv_bfloat16* Al = Ah + TILE_ELEMS;
        __nv_bfloat16* Bh = Al + TILE_ELEMS;
        __nv_bfloat16* Bl = Bh + TILE_ELEMS;

#pragma unroll
        for (int kk = 0; kk < 4; kk++) {
            const int kc = kk * 16 + lc;
            uint32_t bh[4][2], bl[4][2];
#pragma unroll
            for (int nf = 0; nf < 4; nf++) {
                int nrow = wn * 32 + nf * 8 + lr;
                bh[nf][0] = lds_u32(&Bh[nrow * AS_ + kc]);
                bh[nf][1] = lds_u32(&Bh[nrow * AS_ + kc + 8]);
                bl[nf][0] = lds_u32(&Bl[nrow * AS_ + kc]);
                bl[nf][1] = lds_u32(&Bl[nrow * AS_ + kc + 8]);
            }
#pragma unroll
            for (int mf = 0; mf < 4; mf++) {
                int r0 = wm * 64 + mf * 16 + lr;
                uint32_t ah[4], al[4];
                ah[0] = lds_u32(&Ah[r0 * AS_ + kc]);
                ah[1] = lds_u32(&Ah[(r0 + 8) * AS_ + kc]);
                ah[2] = lds_u32(&Ah[r0 * AS_ + kc + 8]);
                ah[3] = lds_u32(&Ah[(r0 + 8) * AS_ + kc + 8]);
                al[0] = lds_u32(&Al[r0 * AS_ + kc]);
                al[1] = lds_u32(&Al[(r0 + 8) * AS_ + kc]);
                al[2] = lds_u32(&Al[r0 * AS_ + kc + 8]);
                al[3] = lds_u32(&Al[(r0 + 8) * AS_ + kc + 8]);
#pragma unroll
                for (int nf = 0; nf < 4; nf++) {
                    mma16816(acc[mf][nf], ah, bh[nf]);
                    mma16816(acc[mf][nf], ah, bl[nf]);
                    mma16816(acc[mf][nf], al, bh[nf]);
                }
            }
        }
        __syncthreads();
    }

#pragma unroll
    for (int mf = 0; mf < 4; mf++) {
#pragma unroll
        for (int nf = 0; nf < 4; nf++) {
            int row = m0 + wm * 64 + mf * 16 + lr;
            int col = n0 + wn * 32 + nf * 8 + lc;
            float b0 = __ldg(&bias[col]), b1 = __ldg(&bias[col + 1]);
            float v0 = acc[mf][nf][0] + b0, v1 = acc[mf][nf][1] + b1;
            float v2 = acc[mf][nf][2] + b0, v3 = acc[mf][nf][3] + b1;
            if (!split_out) {
                float2 p0 = {v0, v1}, p1 = {v2, v3};
                *reinterpret_cast<float2*>(&C[(size_t)row * Nc + col]) = p0;
                *reinterpret_cast<float2*>(&C[(size_t)(row + 8) * Nc + col]) = p1;
            } else {
                __nv_bfloat16 h0 = __float2bfloat16(v0), h1 = __float2bfloat16(v1);
                __nv_bfloat16 h2 = __float2bfloat16(v2), h3 = __float2bfloat16(v3);
                float l0 = v0 - __bfloat162float(h0), l1 = v1 - __bfloat162float(h1);
                float l2 = v2 - __bfloat162float(h2), l3 = v3 - __bfloat162float(h3);
                size_t o0 = (size_t)row * Nc + col, o1 = (size_t)(row + 8) * Nc + col;
                *reinterpret_cast<uint32_t*>(&Chi[o0]) = pack_bf16(__bfloat162float(h0), __bfloat162float(h1));
                *reinterpret_cast<uint32_t*>(&Chi[o1]) = pack_bf16(__bfloat162float(h2), __bfloat162float(h3));
                *reinterpret_cast<uint32_t*>(&Clo[o0]) = pack_bf16(l0, l1);
                *reinterpret_cast<uint32_t*>(&Clo[o1]) = pack_bf16(l2, l3);
            }
        }
    }
}

// ---------------------------------------------------------------------------
// Tensor-core flash attention with 2-stage cp.async K/V pipeline.
// CTA: 64 q-rows, 4 warps, 128 threads, 64-key chunks.
// ---------------------------------------------------------------------------
#define TAS 72
#define ATT_TILE (64 * TAS)
#define ATT_STAGE (4 * ATT_TILE)                    // Kh,Kl,Vh,Vl
#define ATT_SMEM ((2 * ATT_TILE + 2 * ATT_STAGE) * 2)   // 92160 B

__device__ __forceinline__ void cp_att_tile(const __nv_bfloat16* __restrict__ g,
                                            int n0, int coloff,
                                            __nv_bfloat16* dst, int tid)
{
#pragma unroll
    for (int it = 0; it < 4; it++) {
        int idx = tid + it * 128;
        int r = idx >> 3, gq = idx & 7;
        cp_async16(dst + r * TAS + gq * 8,
                   g + (size_t)(n0 + r) * THREE_E + coloff + gq * 8);
    }
}

__global__ void __launch_bounds__(128)
attn_mma(const __nv_bfloat16* __restrict__ qkvh,
         const __nv_bfloat16* __restrict__ qkvl,
         __nv_bfloat16* __restrict__ out_hi,
         __nv_bfloat16* __restrict__ out_lo)
{
    extern __shared__ __nv_bfloat16 smb[];
    __nv_bfloat16* Qh = smb;
    __nv_bfloat16* Ql = Qh + ATT_TILE;
    __nv_bfloat16* KV = Ql + ATT_TILE;   // 2 stages x (Kh,Kl,Vh,Vl)

    const int tid  = threadIdx.x;
    const int wid  = tid >> 5;
    const int lane = tid & 31;
    const int lr = lane >> 2;
    const int lc = (lane & 3) * 2;
    const int q0 = blockIdx.x * 64;
    const int h  = blockIdx.y;
    const int b  = blockIdx.z;
    const int hoff = h * D_;
    const int nbase = b * N_;

    // Q tile via cp.async too (then fragments)
    cp_att_tile(qkvh, nbase + q0, hoff, Qh, tid);
    cp_att_tile(qkvl, nbase + q0, hoff, Ql, tid);
    CP_COMMIT();
    // K/V chunk 0 into stage 0
    {
        __nv_bfloat16* st = KV;
        cp_att_tile(qkvh, nbase, E_ + hoff,     st, tid);
        cp_att_tile(qkvl, nbase, E_ + hoff,     st + ATT_TILE, tid);
        cp_att_tile(qkvh, nbase, 2 * E_ + hoff, st + 2 * ATT_TILE, tid);
        cp_att_tile(qkvl, nbase, 2 * E_ + hoff, st + 3 * ATT_TILE, tid);
        CP_COMMIT();
    }
    CP_WAIT(1);          // Q ready
    __syncthreads();

    uint32_t qh[4][4], ql[4][4];
    const int qrow = wid * 16 + lr;
#pragma unroll
    for (int kc = 0; kc < 4; kc++) {
        int c0 = kc * 16 + lc;
        qh[kc][0] = lds_u32(&Qh[qrow * TAS + c0]);
        qh[kc][1] = lds_u32(&Qh[(qrow + 8) * TAS + c0]);
        qh[kc][2] = lds_u32(&Qh[qrow * TAS + c0 + 8]);
        qh[kc][3] = lds_u32(&Qh[(qrow + 8) * TAS + c0 + 8]);
        ql[kc][0] = lds_u32(&Ql[qrow * TAS + c0]);
        ql[kc][1] = lds_u32(&Ql[(qrow + 8) * TAS + c0]);
        ql[kc][2] = lds_u32(&Ql[qrow * TAS + c0 + 8]);
        ql[kc][3] = lds_u32(&Ql[(qrow + 8) * TAS + c0 + 8]);
    }

    float o[32];
#pragma unroll
    for (int i = 0; i < 32; i++) o[i] = 0.f;
    float m0 = -1e30f, m1 = -1e30f, l0 = 0.f, l1 = 0.f;

    const int lgrp = lane >> 3;
    const int lrow = lane & 7;
    const int key_in = lrow + 8 * (lgrp & 1);
    const int d_in   = 8 * (lgrp >> 1);

    for (int kt = 0; kt < N_ / 64; kt++) {
        if (kt + 1 < N_ / 64) {
            __nv_bfloat16* st = KV + ((kt + 1) & 1) * ATT_STAGE;
            const int kn = nbase + (kt + 1) * 64;
            cp_att_tile(qkvh, kn, E_ + hoff,     st, tid);
            cp_att_tile(qkvl, kn, E_ + hoff,     st + ATT_TILE, tid);
            cp_att_tile(qkvh, kn, 2 * E_ + hoff, st + 2 * ATT_TILE, tid);
            cp_att_tile(qkvl, kn, 2 * E_ + hoff, st + 3 * ATT_TILE, tid);
            CP_COMMIT();
            CP_WAIT(1);
        } else {
            CP_WAIT(0);
        }
        __syncthreads();

        __nv_bfloat16* Kh = KV + (kt & 1) * ATT_STAGE;
        __nv_bfloat16* Kl = Kh + ATT_TILE;
        __nv_bfloat16* Vh = Kl + ATT_TILE;
        __nv_bfloat16* Vl = Vh + ATT_TILE;
        const uint32_t vh_base = smem_u32(Vh);
        const uint32_t vl_base = smem_u32(Vl);

        // Stage 1: S = Q K^T (split-bf16)
        float s[32];
#pragma unroll
        for (int i = 0; i < 32; i++) s[i] = 0.f;
#pragma unroll
        for (int kc = 0; kc < 4; kc++) {
            const int c0 = kc * 16 + lc;
            uint32_t kh[8][2], kl[8][2];
#pragma unroll
            for (int nf = 0; nf < 8; nf++) {
                int nrow = nf * 8 + lr;
                kh[nf][0] = lds_u32(&Kh[nrow * TAS + c0]);
                kh[nf][1] = lds_u32(&Kh[nrow * TAS + c0 + 8]);
                kl[nf][0] = lds_u32(&Kl[nrow * TAS + c0]);
                kl[nf][1] = lds_u32(&Kl[nrow * TAS + c0 + 8]);
            }
#pragma unroll
            for (int nf = 0; nf < 8; nf++) {
                mma16816(&s[nf * 4], qh[kc], kh[nf]);
                mma16816(&s[nf * 4], qh[kc], kl[nf]);
                mma16816(&s[nf * 4], ql[kc], kh[nf]);
            }
        }

        // Online softmax
#pragma unroll
        for (int i = 0; i < 32; i++) s[i] *= 0.125f;
        float r0 = -1e30f, r1 = -1e30f;
#pragma unroll
        for (int nf = 0; nf < 8; nf++) {
            r0 = fmaxf(r0, fmaxf(s[nf * 4 + 0], s[nf * 4 + 1]));
            r1 = fmaxf(r1, fmaxf(s[nf * 4 + 2], s[nf * 4 + 3]));
        }
        r0 = fmaxf(r0, __shfl_xor_sync(0xffffffffu, r0, 1));
        r0 = fmaxf(r0, __shfl_xor_sync(0xffffffffu, r0, 2));
        r1 = fmaxf(r1, __shfl_xor_sync(0xffffffffu, r1, 1));
        r1 = fmaxf(r1, __shfl_xor_sync(0xffffffffu, r1, 2));

        float nm0 = fmaxf(m0, r0), nm1 = fmaxf(m1, r1);
        float a0 = __expf(m0 - nm0), a1 = __expf(m1 - nm1);
        m0 = nm0; m1 = nm1;

        float sum0 = 0.f, sum1 = 0.f;
#pragma unroll
        for (int nf = 0; nf < 8; nf++) {
            s[nf * 4 + 0] = __expf(s[nf * 4 + 0] - m0);
            s[nf * 4 + 1] = __expf(s[nf * 4 + 1] - m0);
            s[nf * 4 + 2] = __expf(s[nf * 4 + 2] - m1);
            s[nf * 4 + 3] = __expf(s[nf * 4 + 3] - m1);
            sum0 += s[nf * 4 + 0] + s[nf * 4 + 1];
            sum1 += s[nf * 4 + 2] + s[nf * 4 + 3];
        }
        sum0 += __shfl_xor_sync(0xffffffffu, sum0, 1);
        sum0 += __shfl_xor_sync(0xffffffffu, sum0, 2);
        sum1 += __shfl_xor_sync(0xffffffffu, sum1, 1);
        sum1 += __shfl_xor_sync(0xffffffffu, sum1, 2);
        l0 = l0 * a0 + sum0;
        l1 = l1 * a1 + sum1;
#pragma unroll
        for (int nf = 0; nf < 8; nf++) {
            o[nf * 4 + 0] *= a0; o[nf * 4 + 1] *= a0;
            o[nf * 4 + 2] *= a1; o[nf * 4 + 3] *= a1;
        }

        // Split P (C-frag layout == A-frag layout)
        uint32_t pha[8], phb[8], pla[8], plb[8];
#pragma unroll
        for (int nf = 0; nf < 8; nf++) {
            float v0 = s[nf * 4 + 0], v1 = s[nf * 4 + 1];
            float v2 = s[nf * 4 + 2], v3 = s[nf * 4 + 3];
            __nv_bfloat16 h0 = __float2bfloat16(v0), h1 = __float2bfloat16(v1);
            __nv_bfloat16 h2 = __float2bfloat16(v2), h3 = __float2bfloat16(v3);
            pha[nf] = pack_bf16(__bfloat162float(h0), __bfloat162float(h1));
            phb[nf] = pack_bf16(__bfloat162float(h2), __bfloat162float(h3));
            pla[nf] = pack_bf16(v0 - __bfloat162float(h0), v1 - __bfloat162float(h1));
            plb[nf] = pack_bf16(v2 - __bfloat162float(h2), v3 - __bfloat162float(h3));
        }

        // Stage 2: O += P V (split x split), V frags via ldmatrix.trans
#pragma unroll
        for (int t = 0; t < 4; t++) {
            uint32_t ah[4] = {pha[2 * t], phb[2 * t], pha[2 * t + 1], phb[2 * t + 1]};
            uint32_t al[4] = {pla[2 * t], plb[2 * t], pla[2 * t + 1], plb[2 * t + 1]};
            const int keyr = t * 16 + key_in;
#pragma unroll
            for (int dp = 0; dp < 4; dp++) {
                const uint32_t off = (uint32_t)(keyr * TAS + dp * 16 + d_in) * 2;
                uint32_t vh[4], vl[4];
                ldmx4_trans(vh, vh_base + off);
                ldmx4_trans(vl, vl_base + off);
                mma16816(&o[(2 * dp) * 4], ah, &vh[0]);
                mma16816(&o[(2 * dp) * 4], ah, &vl[0]);
                mma16816(&o[(2 * dp) * 4], al, &vh[0]);
                mma16816(&o[(2 * dp + 1) * 4], ah, &vh[2]);
                mma16816(&o[(2 * dp + 1) * 4], ah, &vl[2]);
                mma16816(&o[(2 * dp + 1) * 4], al, &vh[2]);
            }
        }
        __syncthreads();
    }

    // Epilogue
    const float inv0 = 1.f / l0, inv1 = 1.f / l1;
#pragma unroll
    for (int nf = 0; nf < 8; nf++) {
        float v0 = o[nf * 4 + 0] * inv0, v1 = o[nf * 4 + 1] * inv0;
        float v2 = o[nf * 4 + 2] * inv1, v3 = o[nf * 4 + 3] * inv1;
        size_t i0 = (size_t)(nbase + q0 + qrow) * E_ + hoff + nf * 8 + lc;
        size_t i1 = (size_t)(nbase + q0 + qrow + 8) * E_ + hoff + nf * 8 + lc;
        __nv_bfloat16 h0 = __float2bfloat16(v0), h1 = __float2bfloat16(v1);
        __nv_bfloat16 h2 = __float2bfloat16(v2), h3 = __float2bfloat16(v3);
        *reinterpret_cast<uint32_t*>(&out_hi[i0]) = pack_bf16(__bfloat162float(h0), __bfloat162float(h1));
        *reinterpret_cast<uint32_t*>(&out_hi[i1]) = pack_bf16(__bfloat162float(h2), __bfloat162float(h3));
        *reinterpret_cast<uint32_t*>(&out_lo[i0]) = pack_bf16(v0 - __bfloat162float(h0), v1 - __bfloat162float(h1));
        *reinterpret_cast<uint32_t*>(&out_lo[i1]) = pack_bf16(v2 - __bfloat162float(h2), v3 - __bfloat162float(h3));
    }
}

// ---------------------------------------------------------------------------
extern "C" void kernel_launch(void* const* d_in, const int* in_sizes, int n_in,
                              void* d_out, int out_size)
{
    const float* x      = (const float*)d_in[0];
    const float* w_qkv  = (const float*)d_in[1];
    const float* b_qkv  = (const float*)d_in[2];
    const float* w_proj = (const float*)d_in[3];
    const float* b_proj = (const float*)d_in[4];
    float* out = (float*)d_out;

    __nv_bfloat16 *ah, *al, *qh, *qlp, *wqh, *wql, *wph, *wpl;
    cudaGetSymbolAddress((void**)&ah,  g_a_hi);
    cudaGetSymbolAddress((void**)&al,  g_a_lo);
    cudaGetSymbolAddress((void**)&qh,  g_qkv_hi);
    cudaGetSymbolAddress((void**)&qlp, g_qkv_lo);
    cudaGetSymbolAddress((void**)&wqh, g_wq_hi);
    cudaGetSymbolAddress((void**)&wql, g_wq_lo);
    cudaGetSymbolAddress((void**)&wph, g_wp_hi);
    cudaGetSymbolAddress((void**)&wpl, g_wp_lo);

    static bool attr_set = false;
    if (!attr_set) {
        cudaFuncSetAttribute(gemm_mma,
                             cudaFuncAttributeMaxDynamicSharedMemorySize, GEMM_SMEM);
        cudaFuncSetAttribute(attn_mma,
                             cudaFuncAttributeMaxDynamicSharedMemorySize, ATT_SMEM);
        attr_set = true;
    }

    // Prep
    {
        int n = M_ROWS * E_;
        split_f32<<<(n + 255) / 256, 256>>>(x, ah, al, n);
    }
    transpose_split<<<dim3(THREE_E / 32, E_ / 32), dim3(32, 8)>>>(w_qkv, wqh, wql, E_, THREE_E);
    transpose_split<<<dim3(E_ / 32, E_ / 32), dim3(32, 8)>>>(w_proj, wph, wpl, E_, E_);

    // 1) QKV gemm, split-bf16 output
    gemm_mma<<<dim3(THREE_E / 128, M_ROWS / 128), 256, GEMM_SMEM>>>(
        ah, al, wqh, wql, b_qkv, nullptr, qh, qlp, THREE_E, E_, 1);

    // 2) Tensor-core flash attention -> split output into ah/al
    attn_mma<<<dim3(N_ / 64, H_, B_), 128, ATT_SMEM>>>(qh, qlp, ah, al);

    // 3) Projection gemm, fp32 output
    gemm_mma<<<dim3(E_ / 128, M_ROWS / 128), 256, GEMM_SMEM>>>(
        ah, al, wph, wpl, b_proj, out, nullptr, nullptr, E_, E_, 0);
}

// round 8
// speedup vs baseline: 1.0028x; 1.0028x over previous
#include <cuda_runtime.h>
#include <cuda_bf16.h>
#include <cstdint>
#include <math.h>

#define B_ 2
#define N_ 2048
#define E_ 1024
#define H_ 16
#define D_ 64
#define THREE_E 3072
#define M_ROWS 4096   // B*N

// ---------------------------------------------------------------------------
// Scratch (__device__ globals; allocation-free rule)
// ---------------------------------------------------------------------------
__device__ __nv_bfloat16 g_a_hi[(size_t)M_ROWS * E_];        // x split, then attn-out split
__device__ __nv_bfloat16 g_a_lo[(size_t)M_ROWS * E_];
__device__ __nv_bfloat16 g_qkv_hi[(size_t)M_ROWS * THREE_E]; // qkv split (gemm1 out)
__device__ __nv_bfloat16 g_qkv_lo[(size_t)M_ROWS * THREE_E];
__device__ __nv_bfloat16 g_wq_hi[(size_t)THREE_E * E_];      // w_qkv^T [Nc,K]
__device__ __nv_bfloat16 g_wq_lo[(size_t)THREE_E * E_];
__device__ __nv_bfloat16 g_wp_hi[(size_t)E_ * E_];           // w_proj^T
__device__ __nv_bfloat16 g_wp_lo[(size_t)E_ * E_];

// ---------------------------------------------------------------------------
// PTX helpers (sm_80+, valid on plain compute_100)
// ---------------------------------------------------------------------------
__device__ __forceinline__ void mma16816(float* c, const uint32_t* a, const uint32_t* b) {
    asm volatile(
        "mma.sync.aligned.m16n8k16.row.col.f32.bf16.bf16.f32 "
        "{%0,%1,%2,%3}, {%4,%5,%6,%7}, {%8,%9}, {%0,%1,%2,%3};"
        : "+f"(c[0]), "+f"(c[1]), "+f"(c[2]), "+f"(c[3])
        : "r"(a[0]), "r"(a[1]), "r"(a[2]), "r"(a[3]), "r"(b[0]), "r"(b[1]));
}
__device__ __forceinline__ uint32_t lds_u32(const __nv_bfloat16* p) {
    return *reinterpret_cast<const uint32_t*>(p);
}
__device__ __forceinline__ void ldmx4_trans(uint32_t* r, uint32_t addr) {
    asm volatile("ldmatrix.sync.aligned.m8n8.x4.trans.shared.b16 {%0,%1,%2,%3}, [%4];"
                 : "=r"(r[0]), "=r"(r[1]), "=r"(r[2]), "=r"(r[3]) : "r"(addr));
}
__device__ __forceinline__ uint32_t smem_u32(const void* p) {
    uint32_t a;
    asm("{ .reg .u64 t; cvta.to.shared.u64 t, %1; cvt.u32.u64 %0, t; }"
        : "=r"(a) : "l"(p));
    return a;
}
__device__ __forceinline__ uint32_t pack_bf16(float a, float b) {
    __nv_bfloat162 v = __floats2bfloat162_rn(a, b);
    return *reinterpret_cast<uint32_t*>(&v);
}
__device__ __forceinline__ void cp_async16(void* smem_dst, const void* gsrc) {
    uint32_t d = smem_u32(smem_dst);
    asm volatile("cp.async.cg.shared.global [%0], [%1], 16;" :: "r"(d), "l"(gsrc));
}
#define CP_COMMIT() asm volatile("cp.async.commit_group;" ::: "memory")
#define CP_WAIT(n)  asm volatile("cp.async.wait_group %0;" :: "n"(n) : "memory")

// ---------------------------------------------------------------------------
// Prep kernels
// ---------------------------------------------------------------------------
__global__ void split_f32(const float* __restrict__ src,
                          __nv_bfloat16* __restrict__ hi,
                          __nv_bfloat16* __restrict__ lo, int n)
{
    int i = blockIdx.x * blockDim.x + threadIdx.x;
    if (i < n) {
        float x = src[i];
        __nv_bfloat16 h = __float2bfloat16(x);
        hi[i] = h;
        lo[i] = __float2bfloat16(x - __bfloat162float(h));
    }
}

__global__ void transpose_split(const float* __restrict__ w,
                                __nv_bfloat16* __restrict__ thi,
                                __nv_bfloat16* __restrict__ tlo,
                                int K, int Nc)
{
    __shared__ float t[32][33];
    int n0 = blockIdx.x * 32, k0 = blockIdx.y * 32;
    int tx = threadIdx.x, ty = threadIdx.y;     // 32 x 8
#pragma unroll
    for (int i = 0; i < 32; i += 8)
        t[ty + i][tx] = w[(size_t)(k0 + ty + i) * Nc + n0 + tx];
    __syncthreads();
#pragma unroll
    for (int i = 0; i < 32; i += 8) {
        float v = t[tx][ty + i];
        __nv_bfloat16 h = __float2bfloat16(v);
        size_t o = (size_t)(n0 + ty + i) * K + k0 + tx;
        thi[o] = h;
        tlo[o] = __float2bfloat16(v - __bfloat162float(h));
    }
}

// ---------------------------------------------------------------------------
// Split-bf16 GEMM: 2-stage cp.async pipeline at K-chunk 32 -> 82KB smem,
// 2 CTAs/SM (cross-CTA overlap + intra-CTA prefetch).
// CTA: 128x128 tile, 256 thr (8 warps, 2m x 4n).
// ---------------------------------------------------------------------------
#define AS_ 40                              // 32 + 8 pad (80 B rows, conflict-free)
#define TILE_ELEMS (128 * AS_)
#define STAGE_ELEMS (4 * TILE_ELEMS)
#define GEMM_SMEM (2 * STAGE_ELEMS * 2)     // 81920 B

__device__ __forceinline__ void cp_tile_g(const __nv_bfloat16* __restrict__ src,
                                          int row0, int K, int k0,
                                          __nv_bfloat16* dst, int tid)
{
#pragma unroll
    for (int it = 0; it < 2; it++) {
        int idx = tid + it * 256;          // 0..511
        int r = idx >> 2, g = idx & 3;     // 128 rows x 4 groups of 8 elems
        cp_async16(dst + r * AS_ + g * 8,
                   src + (size_t)(row0 + r) * K + k0 + g * 8);
    }
}

__global__ void __launch_bounds__(256, 2)
gemm_mma(const __nv_bfloat16* __restrict__ a_hi,
         const __nv_bfloat16* __restrict__ a_lo,
         const __nv_bfloat16* __restrict__ b_hi,
         const __nv_bfloat16* __restrict__ b_lo,
         const float* __restrict__ bias,
         float* __restrict__ C,
         __nv_bfloat16* __restrict__ Chi,
         __nv_bfloat16* __restrict__ Clo,
         int Nc, int K, int split_out)
{
    extern __shared__ __nv_bfloat16 sm[];

    const int tid  = threadIdx.x;
    const int wid  = tid >> 5;
    const int lane = tid & 31;
    const int wm   = wid >> 2;
    const int wn   = wid & 3;
    const int m0   = blockIdx.y * 128;
    const int n0   = blockIdx.x * 128;
    const int lr = lane >> 2;
    const int lc = (lane & 3) * 2;

    float acc[4][4][4];
#pragma unroll
    for (int i = 0; i < 4; i++)
#pragma unroll
        for (int j = 0; j < 4; j++)
#pragma unroll
            for (int q = 0; q < 4; q++) acc[i][j][q] = 0.f;

    const int nchunk = K >> 5;             // K/32

    // Prologue: chunk 0 -> stage 0
    {
        __nv_bfloat16* st = sm;
        cp_tile_g(a_hi, m0, K, 0, st, tid);
        cp_tile_g(a_lo, m0, K, 0, st + TILE_ELEMS, tid);
        cp_tile_g(b_hi, n0, K, 0, st + 2 * TILE_ELEMS, tid);
        cp_tile_g(b_lo, n0, K, 0, st + 3 * TILE_ELEMS, tid);
        CP_COMMIT();
    }

    for (int c = 0; c < nchunk; c++) {
        if (c + 1 < nchunk) {
            __nv_bfloat16* st = sm + ((c + 1) & 1) * STAGE_ELEMS;
            const int k1 = (c + 1) << 5;
            cp_tile_g(a_hi, m0, K, k1, st, tid);
            cp_tile_g(a_lo, m0, K, k1, st + TILE_ELEMS, tid);
            cp_tile_g(b_hi, n0, K, k1, st + 2 * TILE_ELEMS, tid);
            cp_tile_g(b_lo, n0, K, k1, st + 3 * TILE_ELEMS, tid);
            CP_COMMIT();
            CP_WAIT(1);
        } else {
            CP_WAIT(0);
        }
        __syncthreads();

        __nv_bfloat16* Ah = sm + (c & 1) * STAGE_ELEMS;
        __nv_bfloat16* Al = Ah + TILE_ELEMS;
        __nv_bfloat16* Bh = Al + TILE_ELEMS;
        __nv_bfloat16* Bl = Bh + TILE_ELEMS;

#pragma unroll
        for (int kk = 0; kk < 2; kk++) {
            const int kc = kk * 16 + lc;
            uint32_t bh[4][2], bl[4][2];
#pragma unroll
            for (int nf = 0; nf < 4; nf++) {
                int nrow = wn * 32 + nf * 8 + lr;
                bh[nf][0] = lds_u32(&Bh[nrow * AS_ + kc]);
                bh[nf][1] = lds_u32(&Bh[nrow * AS_ + kc + 8]);
                bl[nf][0] = lds_u32(&Bl[nrow * AS_ + kc]);
                bl[nf][1] = lds_u32(&Bl[nrow * AS_ + kc + 8]);
            }
#pragma unroll
            for (int mf = 0; mf < 4; mf++) {
                int r0 = wm * 64 + mf * 16 + lr;
                uint32_t ah[4], al[4];
                ah[0] = lds_u32(&Ah[r0 * AS_ + kc]);
                ah[1] = lds_u32(&Ah[(r0 + 8) * AS_ + kc]);
                ah[2] = lds_u32(&Ah[r0 * AS_ + kc + 8]);
                ah[3] = lds_u32(&Ah[(r0 + 8) * AS_ + kc + 8]);
                al[0] = lds_u32(&Al[r0 * AS_ + kc]);
                al[1] = lds_u32(&Al[(r0 + 8) * AS_ + kc]);
                al[2] = lds_u32(&Al[r0 * AS_ + kc + 8]);
                al[3] = lds_u32(&Al[(r0 + 8) * AS_ + kc + 8]);
#pragma unroll
                for (int nf = 0; nf < 4; nf++) {
                    mma16816(acc[mf][nf], ah, bh[nf]);
                    mma16816(acc[mf][nf], ah, bl[nf]);
                    mma16816(acc[mf][nf], al, bh[nf]);
                }
            }
        }
        __syncthreads();
    }

#pragma unroll
    for (int mf = 0; mf < 4; mf++) {
#pragma unroll
        for (int nf = 0; nf < 4; nf++) {
            int row = m0 + wm * 64 + mf * 16 + lr;
            int col = n0 + wn * 32 + nf * 8 + lc;
            float b0 = __ldg(&bias[col]), b1 = __ldg(&bias[col + 1]);
            float v0 = acc[mf][nf][0] + b0, v1 = acc[mf][nf][1] + b1;
            float v2 = acc[mf][nf][2] + b0, v3 = acc[mf][nf][3] + b1;
            if (!split_out) {
                float2 p0 = {v0, v1}, p1 = {v2, v3};
                *reinterpret_cast<float2*>(&C[(size_t)row * Nc + col]) = p0;
                *reinterpret_cast<float2*>(&C[(size_t)(row + 8) * Nc + col]) = p1;
            } else {
                __nv_bfloat16 h0 = __float2bfloat16(v0), h1 = __float2bfloat16(v1);
                __nv_bfloat16 h2 = __float2bfloat16(v2), h3 = __float2bfloat16(v3);
                float l0 = v0 - __bfloat162float(h0), l1 = v1 - __bfloat162float(h1);
                float l2 = v2 - __bfloat162float(h2), l3 = v3 - __bfloat162float(h3);
                size_t o0 = (size_t)row * Nc + col, o1 = (size_t)(row + 8) * Nc + col;
                *reinterpret_cast<uint32_t*>(&Chi[o0]) = pack_bf16(__bfloat162float(h0), __bfloat162float(h1));
                *reinterpret_cast<uint32_t*>(&Chi[o1]) = pack_bf16(__bfloat162float(h2), __bfloat162float(h3));
                *reinterpret_cast<uint32_t*>(&Clo[o0]) = pack_bf16(l0, l1);
                *reinterpret_cast<uint32_t*>(&Clo[o1]) = pack_bf16(l2, l3);
            }
        }
    }
}

// ---------------------------------------------------------------------------
// Tensor-core flash attention with 2-stage cp.async K/V pipeline.
// (byte-identical to R7 run — proven at ~295us)
// ---------------------------------------------------------------------------
#define TAS 72
#define ATT_TILE (64 * TAS)
#define ATT_STAGE (4 * ATT_TILE)                    // Kh,Kl,Vh,Vl
#define ATT_SMEM ((2 * ATT_TILE + 2 * ATT_STAGE) * 2)   // 92160 B

__device__ __forceinline__ void cp_att_tile(const __nv_bfloat16* __restrict__ g,
                                            int n0, int coloff,
                                            __nv_bfloat16* dst, int tid)
{
#pragma unroll
    for (int it = 0; it < 4; it++) {
        int idx = tid + it * 128;
        int r = idx >> 3, gq = idx & 7;
        cp_async16(dst + r * TAS + gq * 8,
                   g + (size_t)(n0 + r) * THREE_E + coloff + gq * 8);
    }
}

__global__ void __launch_bounds__(128)
attn_mma(const __nv_bfloat16* __restrict__ qkvh,
         const __nv_bfloat16* __restrict__ qkvl,
         __nv_bfloat16* __restrict__ out_hi,
         __nv_bfloat16* __restrict__ out_lo)
{
    extern __shared__ __nv_bfloat16 smb[];
    __nv_bfloat16* Qh = smb;
    __nv_bfloat16* Ql = Qh + ATT_TILE;
    __nv_bfloat16* KV = Ql + ATT_TILE;   // 2 stages x (Kh,Kl,Vh,Vl)

    const int tid  = threadIdx.x;
    const int wid  = tid >> 5;
    const int lane = tid & 31;
    const int lr = lane >> 2;
    const int lc = (lane & 3) * 2;
    const int q0 = blockIdx.x * 64;
    const int h  = blockIdx.y;
    const int b  = blockIdx.z;
    const int hoff = h * D_;
    const int nbase = b * N_;

    cp_att_tile(qkvh, nbase + q0, hoff, Qh, tid);
    cp_att_tile(qkvl, nbase + q0, hoff, Ql, tid);
    CP_COMMIT();
    {
        __nv_bfloat16* st = KV;
        cp_att_tile(qkvh, nbase, E_ + hoff,     st, tid);
        cp_att_tile(qkvl, nbase, E_ + hoff,     st + ATT_TILE, tid);
        cp_att_tile(qkvh, nbase, 2 * E_ + hoff, st + 2 * ATT_TILE, tid);
        cp_att_tile(qkvl, nbase, 2 * E_ + hoff, st + 3 * ATT_TILE, tid);
        CP_COMMIT();
    }
    CP_WAIT(1);
    __syncthreads();

    uint32_t qh[4][4], ql[4][4];
    const int qrow = wid * 16 + lr;
#pragma unroll
    for (int kc = 0; kc < 4; kc++) {
        int c0 = kc * 16 + lc;
        qh[kc][0] = lds_u32(&Qh[qrow * TAS + c0]);
        qh[kc][1] = lds_u32(&Qh[(qrow + 8) * TAS + c0]);
        qh[kc][2] = lds_u32(&Qh[qrow * TAS + c0 + 8]);
        qh[kc][3] = lds_u32(&Qh[(qrow + 8) * TAS + c0 + 8]);
        ql[kc][0] = lds_u32(&Ql[qrow * TAS + c0]);
        ql[kc][1] = lds_u32(&Ql[(qrow + 8) * TAS + c0]);
        ql[kc][2] = lds_u32(&Ql[qrow * TAS + c0 + 8]);
        ql[kc][3] = lds_u32(&Ql[(qrow + 8) * TAS + c0 + 8]);
    }

    float o[32];
#pragma unroll
    for (int i = 0; i < 32; i++) o[i] = 0.f;
    float m0 = -1e30f, m1 = -1e30f, l0 = 0.f, l1 = 0.f;

    const int lgrp = lane >> 3;
    const int lrow = lane & 7;
    const int key_in = lrow + 8 * (lgrp & 1);
    const int d_in   = 8 * (lgrp >> 1);

    for (int kt = 0; kt < N_ / 64; kt++) {
        if (kt + 1 < N_ / 64) {
            __nv_bfloat16* st = KV + ((kt + 1) & 1) * ATT_STAGE;
            const int kn = nbase + (kt + 1) * 64;
            cp_att_tile(qkvh, kn, E_ + hoff,     st, tid);
            cp_att_tile(qkvl, kn, E_ + hoff,     st + ATT_TILE, tid);
            cp_att_tile(qkvh, kn, 2 * E_ + hoff, st + 2 * ATT_TILE, tid);
            cp_att_tile(qkvl, kn, 2 * E_ + hoff, st + 3 * ATT_TILE, tid);
            CP_COMMIT();
            CP_WAIT(1);
        } else {
            CP_WAIT(0);
        }
        __syncthreads();

        __nv_bfloat16* Kh = KV + (kt & 1) * ATT_STAGE;
        __nv_bfloat16* Kl = Kh + ATT_TILE;
        __nv_bfloat16* Vh = Kl + ATT_TILE;
        __nv_bfloat16* Vl = Vh + ATT_TILE;
        const uint32_t vh_base = smem_u32(Vh);
        const uint32_t vl_base = smem_u32(Vl);

        float s[32];
#pragma unroll
        for (int i = 0; i < 32; i++) s[i] = 0.f;
#pragma unroll
        for (int kc = 0; kc < 4; kc++) {
            const int c0 = kc * 16 + lc;
            uint32_t kh[8][2], kl[8][2];
#pragma unroll
            for (int nf = 0; nf < 8; nf++) {
                int nrow = nf * 8 + lr;
                kh[nf][0] = lds_u32(&Kh[nrow * TAS + c0]);
                kh[nf][1] = lds_u32(&Kh[nrow * TAS + c0 + 8]);
                kl[nf][0] = lds_u32(&Kl[nrow * TAS + c0]);
                kl[nf][1] = lds_u32(&Kl[nrow * TAS + c0 + 8]);
            }
#pragma unroll
            for (int nf = 0; nf < 8; nf++) {
                mma16816(&s[nf * 4], qh[kc], kh[nf]);
                mma16816(&s[nf * 4], qh[kc], kl[nf]);
                mma16816(&s[nf * 4], ql[kc], kh[nf]);
            }
        }

#pragma unroll
        for (int i = 0; i < 32; i++) s[i] *= 0.125f;
        float r0 = -1e30f, r1 = -1e30f;
#pragma unroll
        for (int nf = 0; nf < 8; nf++) {
            r0 = fmaxf(r0, fmaxf(s[nf * 4 + 0], s[nf * 4 + 1]));
            r1 = fmaxf(r1, fmaxf(s[nf * 4 + 2], s[nf * 4 + 3]));
        }
        r0 = fmaxf(r0, __shfl_xor_sync(0xffffffffu, r0, 1));
        r0 = fmaxf(r0, __shfl_xor_sync(0xffffffffu, r0, 2));
        r1 = fmaxf(r1, __shfl_xor_sync(0xffffffffu, r1, 1));
        r1 = fmaxf(r1, __shfl_xor_sync(0xffffffffu, r1, 2));

        float nm0 = fmaxf(m0, r0), nm1 = fmaxf(m1, r1);
        float a0 = __expf(m0 - nm0), a1 = __expf(m1 - nm1);
        m0 = nm0; m1 = nm1;

        float sum0 = 0.f, sum1 = 0.f;
#pragma unroll
        for (int nf = 0; nf < 8; nf++) {
            s[nf * 4 + 0] = __expf(s[nf * 4 + 0] - m0);
            s[nf * 4 + 1] = __expf(s[nf * 4 + 1] - m0);
            s[nf * 4 + 2] = __expf(s[nf * 4 + 2] - m1);
            s[nf * 4 + 3] = __expf(s[nf * 4 + 3] - m1);
            sum0 += s[nf * 4 + 0] + s[nf * 4 + 1];
            sum1 += s[nf * 4 + 2] + s[nf * 4 + 3];
        }
        sum0 += __shfl_xor_sync(0xffffffffu, sum0, 1);
        sum0 += __shfl_xor_sync(0xffffffffu, sum0, 2);
        sum1 += __shfl_xor_sync(0xffffffffu, sum1, 1);
        sum1 += __shfl_xor_sync(0xffffffffu, sum1, 2);
        l0 = l0 * a0 + sum0;
        l1 = l1 * a1 + sum1;
#pragma unroll
        for (int nf = 0; nf < 8; nf++) {
            o[nf * 4 + 0] *= a0; o[nf * 4 + 1] *= a0;
            o[nf * 4 + 2] *= a1; o[nf * 4 + 3] *= a1;
        }

        uint32_t pha[8], phb[8], pla[8], plb[8];
#pragma unroll
        for (int nf = 0; nf < 8; nf++) {
            float v0 = s[nf * 4 + 0], v1 = s[nf * 4 + 1];
            float v2 = s[nf * 4 + 2], v3 = s[nf * 4 + 3];
            __nv_bfloat16 h0 = __float2bfloat16(v0), h1 = __float2bfloat16(v1);
            __nv_bfloat16 h2 = __float2bfloat16(v2), h3 = __float2bfloat16(v3);
            pha[nf] = pack_bf16(__bfloat162float(h0), __bfloat162float(h1));
            phb[nf] = pack_bf16(__bfloat162float(h2), __bfloat162float(h3));
            pla[nf] = pack_bf16(v0 - __bfloat162float(h0), v1 - __bfloat162float(h1));
            plb[nf] = pack_bf16(v2 - __bfloat162float(h2), v3 - __bfloat162float(h3));
        }

#pragma unroll
        for (int t = 0; t < 4; t++) {
            uint32_t ah[4] = {pha[2 * t], phb[2 * t], pha[2 * t + 1], phb[2 * t + 1]};
            uint32_t al[4] = {pla[2 * t], plb[2 * t], pla[2 * t + 1], plb[2 * t + 1]};
            const int keyr = t * 16 + key_in;
#pragma unroll
            for (int dp = 0; dp < 4; dp++) {
                const uint32_t off = (uint32_t)(keyr * TAS + dp * 16 + d_in) * 2;
                uint32_t vh[4], vl[4];
                ldmx4_trans(vh, vh_base + off);
                ldmx4_trans(vl, vl_base + off);
                mma16816(&o[(2 * dp) * 4], ah, &vh[0]);
                mma16816(&o[(2 * dp) * 4], ah, &vl[0]);
                mma16816(&o[(2 * dp) * 4], al, &vh[0]);
                mma16816(&o[(2 * dp + 1) * 4], ah, &vh[2]);
                mma16816(&o[(2 * dp + 1) * 4], ah, &vl[2]);
                mma16816(&o[(2 * dp + 1) * 4], al, &vh[2]);
            }
        }
        __syncthreads();
    }

    const float inv0 = 1.f / l0, inv1 = 1.f / l1;
#pragma unroll
    for (int nf = 0; nf < 8; nf++) {
        float v0 = o[nf * 4 + 0] * inv0, v1 = o[nf * 4 + 1] * inv0;
        float v2 = o[nf * 4 + 2] * inv1, v3 = o[nf * 4 + 3] * inv1;
        size_t i0 = (size_t)(nbase + q0 + qrow) * E_ + hoff + nf * 8 + lc;
        size_t i1 = (size_t)(nbase + q0 + qrow + 8) * E_ + hoff + nf * 8 + lc;
        __nv_bfloat16 h0 = __float2bfloat16(v0), h1 = __float2bfloat16(v1);
        __nv_bfloat16 h2 = __float2bfloat16(v2), h3 = __float2bfloat16(v3);
        *reinterpret_cast<uint32_t*>(&out_hi[i0]) = pack_bf16(__bfloat162float(h0), __bfloat162float(h1));
        *reinterpret_cast<uint32_t*>(&out_hi[i1]) = pack_bf16(__bfloat162float(h2), __bfloat162float(h3));
        *reinterpret_cast<uint32_t*>(&out_lo[i0]) = pack_bf16(v0 - __bfloat162float(h0), v1 - __bfloat162float(h1));
        *reinterpret_cast<uint32_t*>(&out_lo[i1]) = pack_bf16(v2 - __bfloat162float(h2), v3 - __bfloat162float(h3));
    }
}

// ---------------------------------------------------------------------------
extern "C" void kernel_launch(void* const* d_in, const int* in_sizes, int n_in,
                              void* d_out, int out_size)
{
    const float* x      = (const float*)d_in[0];
    const float* w_qkv  = (const float*)d_in[1];
    const float* b_qkv  = (const float*)d_in[2];
    const float* w_proj = (const float*)d_in[3];
    const float* b_proj = (const float*)d_in[4];
    float* out = (float*)d_out;

    __nv_bfloat16 *ah, *al, *qh, *qlp, *wqh, *wql, *wph, *wpl;
    cudaGetSymbolAddress((void**)&ah,  g_a_hi);
    cudaGetSymbolAddress((void**)&al,  g_a_lo);
    cudaGetSymbolAddress((void**)&qh,  g_qkv_hi);
    cudaGetSymbolAddress((void**)&qlp, g_qkv_lo);
    cudaGetSymbolAddress((void**)&wqh, g_wq_hi);
    cudaGetSymbolAddress((void**)&wql, g_wq_lo);
    cudaGetSymbolAddress((void**)&wph, g_wp_hi);
    cudaGetSymbolAddress((void**)&wpl, g_wp_lo);

    static bool attr_set = false;
    if (!attr_set) {
        cudaFuncSetAttribute(gemm_mma,
                             cudaFuncAttributeMaxDynamicSharedMemorySize, GEMM_SMEM);
        cudaFuncSetAttribute(attn_mma,
                             cudaFuncAttributeMaxDynamicSharedMemorySize, ATT_SMEM);
        attr_set = true;
    }

    // Prep
    {
        int n = M_ROWS * E_;
        split_f32<<<(n + 255) / 256, 256>>>(x, ah, al, n);
    }
    transpose_split<<<dim3(THREE_E / 32, E_ / 32), dim3(32, 8)>>>(w_qkv, wqh, wql, E_, THREE_E);
    transpose_split<<<dim3(E_ / 32, E_ / 32), dim3(32, 8)>>>(w_proj, wph, wpl, E_, E_);

    // 1) QKV gemm, split-bf16 output
    gemm_mma<<<dim3(THREE_E / 128, M_ROWS / 128), 256, GEMM_SMEM>>>(
        ah, al, wqh, wql, b_qkv, nullptr, qh, qlp, THREE_E, E_, 1);

    // 2) Tensor-core flash attention -> split output into ah/al
    attn_mma<<<dim3(N_ / 64, H_, B_), 128, ATT_SMEM>>>(qh, qlp, ah, al);

    // 3) Projection gemm, fp32 output
    gemm_mma<<<dim3(E_ / 128, M_ROWS / 128), 256, GEMM_SMEM>>>(
        ah, al, wph, wpl, b_proj, out, nullptr, nullptr, E_, E_, 0);
}

// round 9
// speedup vs baseline: 1.0221x; 1.0192x over previous
#include <cuda_runtime.h>
#include <cuda_bf16.h>
#include <cstdint>
#include <math.h>

#define B_ 2
#define N_ 2048
#define E_ 1024
#define H_ 16
#define D_ 64
#define THREE_E 3072
#define M_ROWS 4096   // B*N

// ---------------------------------------------------------------------------
// Scratch (__device__ globals; allocation-free rule)
// ---------------------------------------------------------------------------
__device__ __nv_bfloat16 g_a_hi[(size_t)M_ROWS * E_];        // x split, then attn-out split
__device__ __nv_bfloat16 g_a_lo[(size_t)M_ROWS * E_];
__device__ __nv_bfloat16 g_qkv_hi[(size_t)M_ROWS * THREE_E]; // qkv split (gemm1 out)
__device__ __nv_bfloat16 g_qkv_lo[(size_t)M_ROWS * THREE_E];
__device__ __nv_bfloat16 g_wq_hi[(size_t)THREE_E * E_];      // w_qkv^T [Nc,K]
__device__ __nv_bfloat16 g_wq_lo[(size_t)THREE_E * E_];
__device__ __nv_bfloat16 g_wp_hi[(size_t)E_ * E_];           // w_proj^T
__device__ __nv_bfloat16 g_wp_lo[(size_t)E_ * E_];

// ---------------------------------------------------------------------------
// PTX helpers (sm_80+, valid on plain compute_100)
// ---------------------------------------------------------------------------
__device__ __forceinline__ void mma16816(float* c, const uint32_t* a, const uint32_t* b) {
    asm volatile(
        "mma.sync.aligned.m16n8k16.row.col.f32.bf16.bf16.f32 "
        "{%0,%1,%2,%3}, {%4,%5,%6,%7}, {%8,%9}, {%0,%1,%2,%3};"
        : "+f"(c[0]), "+f"(c[1]), "+f"(c[2]), "+f"(c[3])
        : "r"(a[0]), "r"(a[1]), "r"(a[2]), "r"(a[3]), "r"(b[0]), "r"(b[1]));
}
__device__ __forceinline__ uint32_t lds_u32(const __nv_bfloat16* p) {
    return *reinterpret_cast<const uint32_t*>(p);
}
__device__ __forceinline__ void ldmx4_trans(uint32_t* r, uint32_t addr) {
    asm volatile("ldmatrix.sync.aligned.m8n8.x4.trans.shared.b16 {%0,%1,%2,%3}, [%4];"
                 : "=r"(r[0]), "=r"(r[1]), "=r"(r[2]), "=r"(r[3]) : "r"(addr));
}
__device__ __forceinline__ uint32_t smem_u32(const void* p) {
    uint32_t a;
    asm("{ .reg .u64 t; cvta.to.shared.u64 t, %1; cvt.u32.u64 %0, t; }"
        : "=r"(a) : "l"(p));
    return a;
}
__device__ __forceinline__ uint32_t pack_bf16(float a, float b) {
    __nv_bfloat162 v = __floats2bfloat162_rn(a, b);
    return *reinterpret_cast<uint32_t*>(&v);
}
__device__ __forceinline__ void cp_async16(void* smem_dst, const void* gsrc) {
    uint32_t d = smem_u32(smem_dst);
    asm volatile("cp.async.cg.shared.global [%0], [%1], 16;" :: "r"(d), "l"(gsrc));
}
#define CP_COMMIT() asm volatile("cp.async.commit_group;" ::: "memory")
#define CP_WAIT(n)  asm volatile("cp.async.wait_group %0;" :: "n"(n) : "memory")

// ---------------------------------------------------------------------------
// Prep kernels
// ---------------------------------------------------------------------------
__global__ void split_f32(const float* __restrict__ src,
                          __nv_bfloat16* __restrict__ hi,
                          __nv_bfloat16* __restrict__ lo, int n)
{
    int i = blockIdx.x * blockDim.x + threadIdx.x;
    if (i < n) {
        float x = src[i];
        __nv_bfloat16 h = __float2bfloat16(x);
        hi[i] = h;
        lo[i] = __float2bfloat16(x - __bfloat162float(h));
    }
}

__global__ void transpose_split(const float* __restrict__ w,
                                __nv_bfloat16* __restrict__ thi,
                                __nv_bfloat16* __restrict__ tlo,
                                int K, int Nc)
{
    __shared__ float t[32][33];
    int n0 = blockIdx.x * 32, k0 = blockIdx.y * 32;
    int tx = threadIdx.x, ty = threadIdx.y;     // 32 x 8
#pragma unroll
    for (int i = 0; i < 32; i += 8)
        t[ty + i][tx] = w[(size_t)(k0 + ty + i) * Nc + n0 + tx];
    __syncthreads();
#pragma unroll
    for (int i = 0; i < 32; i += 8) {
        float v = t[tx][ty + i];
        __nv_bfloat16 h = __float2bfloat16(v);
        size_t o = (size_t)(n0 + ty + i) * K + k0 + tx;
        thi[o] = h;
        tlo[o] = __float2bfloat16(v - __bfloat162float(h));
    }
}

// ---------------------------------------------------------------------------
// Split-bf16 GEMM — R5 synchronous version (proven fastest: 262us / 88us).
// CTA: 128x128 tile, 256 thr (8 warps, 2m x 4n), K chunk 64, 2 CTAs/SM.
// ---------------------------------------------------------------------------
#define AS_ 72
#define TILE_ELEMS (128 * AS_)
#define GEMM_SMEM (4 * TILE_ELEMS * 2)   // 73728 B

__device__ __forceinline__ void load_tile(const __nv_bfloat16* __restrict__ src,
                                          int row0, int K, int k0,
                                          __nv_bfloat16* dst, int tid)
{
#pragma unroll
    for (int it = 0; it < 4; it++) {
        int idx = tid + it * 256;
        int r = idx >> 3, g = idx & 7;
        uint4 v = *reinterpret_cast<const uint4*>(
            src + (size_t)(row0 + r) * K + k0 + g * 8);
        *reinterpret_cast<uint4*>(dst + r * AS_ + g * 8) = v;
    }
}

__global__ void __launch_bounds__(256, 2)
gemm_mma(const __nv_bfloat16* __restrict__ a_hi,
         const __nv_bfloat16* __restrict__ a_lo,
         const __nv_bfloat16* __restrict__ b_hi,
         const __nv_bfloat16* __restrict__ b_lo,
         const float* __restrict__ bias,
         float* __restrict__ C,
         __nv_bfloat16* __restrict__ Chi,
         __nv_bfloat16* __restrict__ Clo,
         int Nc, int K, int split_out)
{
    extern __shared__ __nv_bfloat16 sm[];
    __nv_bfloat16* Ah = sm;
    __nv_bfloat16* Al = Ah + TILE_ELEMS;
    __nv_bfloat16* Bh = Al + TILE_ELEMS;
    __nv_bfloat16* Bl = Bh + TILE_ELEMS;

    const int tid  = threadIdx.x;
    const int wid  = tid >> 5;
    const int lane = tid & 31;
    const int wm   = wid >> 2;
    const int wn   = wid & 3;
    const int m0   = blockIdx.y * 128;
    const int n0   = blockIdx.x * 128;
    const int lr = lane >> 2;
    const int lc = (lane & 3) * 2;

    float acc[4][4][4];
#pragma unroll
    for (int i = 0; i < 4; i++)
#pragma unroll
        for (int j = 0; j < 4; j++)
#pragma unroll
            for (int q = 0; q < 4; q++) acc[i][j][q] = 0.f;

    const int nchunk = K >> 6;
    for (int c = 0; c < nchunk; c++) {
        const int k0 = c << 6;
        __syncthreads();
        load_tile(a_hi, m0, K, k0, Ah, tid);
        load_tile(a_lo, m0, K, k0, Al, tid);
        load_tile(b_hi, n0, K, k0, Bh, tid);
        load_tile(b_lo, n0, K, k0, Bl, tid);
        __syncthreads();

#pragma unroll
        for (int kk = 0; kk < 4; kk++) {
            const int kc = kk * 16 + lc;
            uint32_t bh[4][2], bl[4][2];
#pragma unroll
            for (int nf = 0; nf < 4; nf++) {
                int nrow = wn * 32 + nf * 8 + lr;
                bh[nf][0] = lds_u32(&Bh[nrow * AS_ + kc]);
                bh[nf][1] = lds_u32(&Bh[nrow * AS_ + kc + 8]);
                bl[nf][0] = lds_u32(&Bl[nrow * AS_ + kc]);
                bl[nf][1] = lds_u32(&Bl[nrow * AS_ + kc + 8]);
            }
#pragma unroll
            for (int mf = 0; mf < 4; mf++) {
                int r0 = wm * 64 + mf * 16 + lr;
                uint32_t ah[4], al[4];
                ah[0] = lds_u32(&Ah[r0 * AS_ + kc]);
                ah[1] = lds_u32(&Ah[(r0 + 8) * AS_ + kc]);
                ah[2] = lds_u32(&Ah[r0 * AS_ + kc + 8]);
                ah[3] = lds_u32(&Ah[(r0 + 8) * AS_ + kc + 8]);
                al[0] = lds_u32(&Al[r0 * AS_ + kc]);
                al[1] = lds_u32(&Al[(r0 + 8) * AS_ + kc]);
                al[2] = lds_u32(&Al[r0 * AS_ + kc + 8]);
                al[3] = lds_u32(&Al[(r0 + 8) * AS_ + kc + 8]);
#pragma unroll
                for (int nf = 0; nf < 4; nf++) {
                    mma16816(acc[mf][nf], ah, bh[nf]);
                    mma16816(acc[mf][nf], ah, bl[nf]);
                    mma16816(acc[mf][nf], al, bh[nf]);
                }
            }
        }
    }

#pragma unroll
    for (int mf = 0; mf < 4; mf++) {
#pragma unroll
        for (int nf = 0; nf < 4; nf++) {
            int row = m0 + wm * 64 + mf * 16 + lr;
            int col = n0 + wn * 32 + nf * 8 + lc;
            float b0 = __ldg(&bias[col]), b1 = __ldg(&bias[col + 1]);
            float v0 = acc[mf][nf][0] + b0, v1 = acc[mf][nf][1] + b1;
            float v2 = acc[mf][nf][2] + b0, v3 = acc[mf][nf][3] + b1;
            if (!split_out) {
                float2 p0 = {v0, v1}, p1 = {v2, v3};
                *reinterpret_cast<float2*>(&C[(size_t)row * Nc + col]) = p0;
                *reinterpret_cast<float2*>(&C[(size_t)(row + 8) * Nc + col]) = p1;
            } else {
                __nv_bfloat16 h0 = __float2bfloat16(v0), h1 = __float2bfloat16(v1);
                __nv_bfloat16 h2 = __float2bfloat16(v2), h3 = __float2bfloat16(v3);
                float l0 = v0 - __bfloat162float(h0), l1 = v1 - __bfloat162float(h1);
                float l2 = v2 - __bfloat162float(h2), l3 = v3 - __bfloat162float(h3);
                size_t o0 = (size_t)row * Nc + col, o1 = (size_t)(row + 8) * Nc + col;
                *reinterpret_cast<uint32_t*>(&Chi[o0]) = pack_bf16(__bfloat162float(h0), __bfloat162float(h1));
                *reinterpret_cast<uint32_t*>(&Chi[o1]) = pack_bf16(__bfloat162float(h2), __bfloat162float(h3));
                *reinterpret_cast<uint32_t*>(&Clo[o0]) = pack_bf16(l0, l1);
                *reinterpret_cast<uint32_t*>(&Clo[o1]) = pack_bf16(l2, l3);
            }
        }
    }
}

// ---------------------------------------------------------------------------
// Tensor-core flash attention, WIDENED: 128 q-rows / 8 warps / 256 threads.
// One K/V tile load now feeds 8 warps (2x compute per byte), 2-stage cp.async.
// ---------------------------------------------------------------------------
#define TAS 72
#define ATT_QTILE (128 * TAS)               // Q: 128 rows
#define ATT_KTILE (64 * TAS)                // K/V: 64 rows
#define ATT_STAGE (4 * ATT_KTILE)           // Kh,Kl,Vh,Vl
#define ATT_SMEM ((2 * ATT_QTILE + 2 * ATT_STAGE) * 2)   // 110592 B

__device__ __forceinline__ void cp_att_q(const __nv_bfloat16* __restrict__ g,
                                         int n0, int coloff,
                                         __nv_bfloat16* dst, int tid)
{
#pragma unroll
    for (int it = 0; it < 4; it++) {
        int idx = tid + it * 256;            // 0..1023 : 128 rows x 8 groups
        int r = idx >> 3, gq = idx & 7;
        cp_async16(dst + r * TAS + gq * 8,
                   g + (size_t)(n0 + r) * THREE_E + coloff + gq * 8);
    }
}
__device__ __forceinline__ void cp_att_kv(const __nv_bfloat16* __restrict__ g,
                                          int n0, int coloff,
                                          __nv_bfloat16* dst, int tid)
{
#pragma unroll
    for (int it = 0; it < 2; it++) {
        int idx = tid + it * 256;            // 0..511 : 64 rows x 8 groups
        int r = idx >> 3, gq = idx & 7;
        cp_async16(dst + r * TAS + gq * 8,
                   g + (size_t)(n0 + r) * THREE_E + coloff + gq * 8);
    }
}

__global__ void __launch_bounds__(256, 2)
attn_mma(const __nv_bfloat16* __restrict__ qkvh,
         const __nv_bfloat16* __restrict__ qkvl,
         __nv_bfloat16* __restrict__ out_hi,
         __nv_bfloat16* __restrict__ out_lo)
{
    extern __shared__ __nv_bfloat16 smb[];
    __nv_bfloat16* Qh = smb;
    __nv_bfloat16* Ql = Qh + ATT_QTILE;
    __nv_bfloat16* KV = Ql + ATT_QTILE;   // 2 stages x (Kh,Kl,Vh,Vl)

    const int tid  = threadIdx.x;
    const int wid  = tid >> 5;            // 0..7 : q-rows wid*16..+15
    const int lane = tid & 31;
    const int lr = lane >> 2;
    const int lc = (lane & 3) * 2;
    const int q0 = blockIdx.x * 128;
    const int h  = blockIdx.y;
    const int b  = blockIdx.z;
    const int hoff = h * D_;
    const int nbase = b * N_;

    cp_att_q(qkvh, nbase + q0, hoff, Qh, tid);
    cp_att_q(qkvl, nbase + q0, hoff, Ql, tid);
    CP_COMMIT();
    {
        __nv_bfloat16* st = KV;
        cp_att_kv(qkvh, nbase, E_ + hoff,     st, tid);
        cp_att_kv(qkvl, nbase, E_ + hoff,     st + ATT_KTILE, tid);
        cp_att_kv(qkvh, nbase, 2 * E_ + hoff, st + 2 * ATT_KTILE, tid);
        cp_att_kv(qkvl, nbase, 2 * E_ + hoff, st + 3 * ATT_KTILE, tid);
        CP_COMMIT();
    }
    CP_WAIT(1);          // Q ready
    __syncthreads();

    uint32_t qh[4][4], ql[4][4];
    const int qrow = wid * 16 + lr;
#pragma unroll
    for (int kc = 0; kc < 4; kc++) {
        int c0 = kc * 16 + lc;
        qh[kc][0] = lds_u32(&Qh[qrow * TAS + c0]);
        qh[kc][1] = lds_u32(&Qh[(qrow + 8) * TAS + c0]);
        qh[kc][2] = lds_u32(&Qh[qrow * TAS + c0 + 8]);
        qh[kc][3] = lds_u32(&Qh[(qrow + 8) * TAS + c0 + 8]);
        ql[kc][0] = lds_u32(&Ql[qrow * TAS + c0]);
        ql[kc][1] = lds_u32(&Ql[(qrow + 8) * TAS + c0]);
        ql[kc][2] = lds_u32(&Ql[qrow * TAS + c0 + 8]);
        ql[kc][3] = lds_u32(&Ql[(qrow + 8) * TAS + c0 + 8]);
    }

    float o[32];
#pragma unroll
    for (int i = 0; i < 32; i++) o[i] = 0.f;
    float m0 = -1e30f, m1 = -1e30f, l0 = 0.f, l1 = 0.f;

    const int lgrp = lane >> 3;
    const int lrow = lane & 7;
    const int key_in = lrow + 8 * (lgrp & 1);
    const int d_in   = 8 * (lgrp >> 1);

    for (int kt = 0; kt < N_ / 64; kt++) {
        if (kt + 1 < N_ / 64) {
            __nv_bfloat16* st = KV + ((kt + 1) & 1) * ATT_STAGE;
            const int kn = nbase + (kt + 1) * 64;
            cp_att_kv(qkvh, kn, E_ + hoff,     st, tid);
            cp_att_kv(qkvl, kn, E_ + hoff,     st + ATT_KTILE, tid);
            cp_att_kv(qkvh, kn, 2 * E_ + hoff, st + 2 * ATT_KTILE, tid);
            cp_att_kv(qkvl, kn, 2 * E_ + hoff, st + 3 * ATT_KTILE, tid);
            CP_COMMIT();
            CP_WAIT(1);
        } else {
            CP_WAIT(0);
        }
        __syncthreads();

        __nv_bfloat16* Kh = KV + (kt & 1) * ATT_STAGE;
        __nv_bfloat16* Kl = Kh + ATT_KTILE;
        __nv_bfloat16* Vh = Kl + ATT_KTILE;
        __nv_bfloat16* Vl = Vh + ATT_KTILE;
        const uint32_t vh_base = smem_u32(Vh);
        const uint32_t vl_base = smem_u32(Vl);

        // Stage 1: S = Q K^T (split-bf16)
        float s[32];
#pragma unroll
        for (int i = 0; i < 32; i++) s[i] = 0.f;
#pragma unroll
        for (int kc = 0; kc < 4; kc++) {
            const int c0 = kc * 16 + lc;
            uint32_t kh[8][2], kl[8][2];
#pragma unroll
            for (int nf = 0; nf < 8; nf++) {
                int nrow = nf * 8 + lr;
                kh[nf][0] = lds_u32(&Kh[nrow * TAS + c0]);
                kh[nf][1] = lds_u32(&Kh[nrow * TAS + c0 + 8]);
                kl[nf][0] = lds_u32(&Kl[nrow * TAS + c0]);
                kl[nf][1] = lds_u32(&Kl[nrow * TAS + c0 + 8]);
            }
#pragma unroll
            for (int nf = 0; nf < 8; nf++) {
                mma16816(&s[nf * 4], qh[kc], kh[nf]);
                mma16816(&s[nf * 4], qh[kc], kl[nf]);
                mma16816(&s[nf * 4], ql[kc], kh[nf]);
            }
        }

        // Online softmax
#pragma unroll
        for (int i = 0; i < 32; i++) s[i] *= 0.125f;
        float r0 = -1e30f, r1 = -1e30f;
#pragma unroll
        for (int nf = 0; nf < 8; nf++) {
            r0 = fmaxf(r0, fmaxf(s[nf * 4 + 0], s[nf * 4 + 1]));
            r1 = fmaxf(r1, fmaxf(s[nf * 4 + 2], s[nf * 4 + 3]));
        }
        r0 = fmaxf(r0, __shfl_xor_sync(0xffffffffu, r0, 1));
        r0 = fmaxf(r0, __shfl_xor_sync(0xffffffffu, r0, 2));
        r1 = fmaxf(r1, __shfl_xor_sync(0xffffffffu, r1, 1));
        r1 = fmaxf(r1, __shfl_xor_sync(0xffffffffu, r1, 2));

        float nm0 = fmaxf(m0, r0), nm1 = fmaxf(m1, r1);
        float a0 = __expf(m0 - nm0), a1 = __expf(m1 - nm1);
        m0 = nm0; m1 = nm1;

        float sum0 = 0.f, sum1 = 0.f;
#pragma unroll
        for (int nf = 0; nf < 8; nf++) {
            s[nf * 4 + 0] = __expf(s[nf * 4 + 0] - m0);
            s[nf * 4 + 1] = __expf(s[nf * 4 + 1] - m0);
            s[nf * 4 + 2] = __expf(s[nf * 4 + 2] - m1);
            s[nf * 4 + 3] = __expf(s[nf * 4 + 3] - m1);
            sum0 += s[nf * 4 + 0] + s[nf * 4 + 1];
            sum1 += s[nf * 4 + 2] + s[nf * 4 + 3];
        }
        sum0 += __shfl_xor_sync(0xffffffffu, sum0, 1);
        sum0 += __shfl_xor_sync(0xffffffffu, sum0, 2);
        sum1 += __shfl_xor_sync(0xffffffffu, sum1, 1);
        sum1 += __shfl_xor_sync(0xffffffffu, sum1, 2);
        l0 = l0 * a0 + sum0;
        l1 = l1 * a1 + sum1;
#pragma unroll
        for (int nf = 0; nf < 8; nf++) {
            o[nf * 4 + 0] *= a0; o[nf * 4 + 1] *= a0;
            o[nf * 4 + 2] *= a1; o[nf * 4 + 3] *= a1;
        }

        // Split P (C-frag layout == A-frag layout)
        uint32_t pha[8], phb[8], pla[8], plb[8];
#pragma unroll
        for (int nf = 0; nf < 8; nf++) {
            float v0 = s[nf * 4 + 0], v1 = s[nf * 4 + 1];
            float v2 = s[nf * 4 + 2], v3 = s[nf * 4 + 3];
            __nv_bfloat16 h0 = __float2bfloat16(v0), h1 = __float2bfloat16(v1);
            __nv_bfloat16 h2 = __float2bfloat16(v2), h3 = __float2bfloat16(v3);
            pha[nf] = pack_bf16(__bfloat162float(h0), __bfloat162float(h1));
            phb[nf] = pack_bf16(__bfloat162float(h2), __bfloat162float(h3));
            pla[nf] = pack_bf16(v0 - __bfloat162float(h0), v1 - __bfloat162float(h1));
            plb[nf] = pack_bf16(v2 - __bfloat162float(h2), v3 - __bfloat162float(h3));
        }

        // Stage 2: O += P V, V frags via ldmatrix.trans
#pragma unroll
        for (int t = 0; t < 4; t++) {
            uint32_t ah[4] = {pha[2 * t], phb[2 * t], pha[2 * t + 1], phb[2 * t + 1]};
            uint32_t al[4] = {pla[2 * t], plb[2 * t], pla[2 * t + 1], plb[2 * t + 1]};
            const int keyr = t * 16 + key_in;
#pragma unroll
            for (int dp = 0; dp < 4; dp++) {
                const uint32_t off = (uint32_t)(keyr * TAS + dp * 16 + d_in) * 2;
                uint32_t vh[4], vl[4];
                ldmx4_trans(vh, vh_base + off);
                ldmx4_trans(vl, vl_base + off);
                mma16816(&o[(2 * dp) * 4], ah, &vh[0]);
                mma16816(&o[(2 * dp) * 4], ah, &vl[0]);
                mma16816(&o[(2 * dp) * 4], al, &vh[0]);
                mma16816(&o[(2 * dp + 1) * 4], ah, &vh[2]);
                mma16816(&o[(2 * dp + 1) * 4], ah, &vl[2]);
                mma16816(&o[(2 * dp + 1) * 4], al, &vh[2]);
            }
        }
        __syncthreads();
    }

    // Epilogue
    const float inv0 = 1.f / l0, inv1 = 1.f / l1;
#pragma unroll
    for (int nf = 0; nf < 8; nf++) {
        float v0 = o[nf * 4 + 0] * inv0, v1 = o[nf * 4 + 1] * inv0;
        float v2 = o[nf * 4 + 2] * inv1, v3 = o[nf * 4 + 3] * inv1;
        size_t i0 = (size_t)(nbase + q0 + qrow) * E_ + hoff + nf * 8 + lc;
        size_t i1 = (size_t)(nbase + q0 + qrow + 8) * E_ + hoff + nf * 8 + lc;
        __nv_bfloat16 h0 = __float2bfloat16(v0), h1 = __float2bfloat16(v1);
        __nv_bfloat16 h2 = __float2bfloat16(v2), h3 = __float2bfloat16(v3);
        *reinterpret_cast<uint32_t*>(&out_hi[i0]) = pack_bf16(__bfloat162float(h0), __bfloat162float(h1));
        *reinterpret_cast<uint32_t*>(&out_hi[i1]) = pack_bf16(__bfloat162float(h2), __bfloat162float(h3));
        *reinterpret_cast<uint32_t*>(&out_lo[i0]) = pack_bf16(v0 - __bfloat162float(h0), v1 - __bfloat162float(h1));
        *reinterpret_cast<uint32_t*>(&out_lo[i1]) = pack_bf16(v2 - __bfloat162float(h2), v3 - __bfloat162float(h3));
    }
}

// ---------------------------------------------------------------------------
extern "C" void kernel_launch(void* const* d_in, const int* in_sizes, int n_in,
                              void* d_out, int out_size)
{
    const float* x      = (const float*)d_in[0];
    const float* w_qkv  = (const float*)d_in[1];
    const float* b_qkv  = (const float*)d_in[2];
    const float* w_proj = (const float*)d_in[3];
    const float* b_proj = (const float*)d_in[4];
    float* out = (float*)d_out;

    __nv_bfloat16 *ah, *al, *qh, *qlp, *wqh, *wql, *wph, *wpl;
    cudaGetSymbolAddress((void**)&ah,  g_a_hi);
    cudaGetSymbolAddress((void**)&al,  g_a_lo);
    cudaGetSymbolAddress((void**)&qh,  g_qkv_hi);
    cudaGetSymbolAddress((void**)&qlp, g_qkv_lo);
    cudaGetSymbolAddress((void**)&wqh, g_wq_hi);
    cudaGetSymbolAddress((void**)&wql, g_wq_lo);
    cudaGetSymbolAddress((void**)&wph, g_wp_hi);
    cudaGetSymbolAddress((void**)&wpl, g_wp_lo);

    static bool attr_set = false;
    if (!attr_set) {
        cudaFuncSetAttribute(gemm_mma,
                             cudaFuncAttributeMaxDynamicSharedMemorySize, GEMM_SMEM);
        cudaFuncSetAttribute(attn_mma,
                             cudaFuncAttributeMaxDynamicSharedMemorySize, ATT_SMEM);
        attr_set = true;
    }

    // Prep
    {
        int n = M_ROWS * E_;
        split_f32<<<(n + 255) / 256, 256>>>(x, ah, al, n);
    }
    transpose_split<<<dim3(THREE_E / 32, E_ / 32), dim3(32, 8)>>>(w_qkv, wqh, wql, E_, THREE_E);
    transpose_split<<<dim3(E_ / 32, E_ / 32), dim3(32, 8)>>>(w_proj, wph, wpl, E_, E_);

    // 1) QKV gemm, split-bf16 output
    gemm_mma<<<dim3(THREE_E / 128, M_ROWS / 128), 256, GEMM_SMEM>>>(
        ah, al, wqh, wql, b_qkv, nullptr, qh, qlp, THREE_E, E_, 1);

    // 2) Tensor-core flash attention (128 q-rows/CTA) -> split output
    attn_mma<<<dim3(N_ / 128, H_, B_), 256, ATT_SMEM>>>(qh, qlp, ah, al);

    // 3) Projection gemm, fp32 output
    gemm_mma<<<dim3(E_ / 128, M_ROWS / 128), 256, GEMM_SMEM>>>(
        ah, al, wph, wpl, b_proj, out, nullptr, nullptr, E_, E_, 0);
}